// round 17
// baseline (speedup 1.0000x reference)
#include <cuda_runtime.h>
#include <cuda_fp16.h>
#include <cstdint>

// ---------------- problem constants ----------------
#define NUM_E    64
#define IN_F     512
#define OUT_F    512
#define NTOK     131072
#define CAPACITY 3072

// ---------------- tiling ----------------
#define TM 128
#define TN 128                 // per n-tile; CTA loops over all 4 n-tiles
#define KC 64                  // K chunk (64 fp16 = 128B row)
#define NCH (IN_F / KC)        // 8
#define NT  (OUT_F / TN)       // 4 n-tiles per CTA
#define NCW (NT * NCH)         // 32 W-chunk iterations
#define THREADS 256            // 8 warps, warp tile 64x32 (2 M-groups x 4 N-groups)
#define WSTAGE 4               // W ring depth
#define MTILES (CAPACITY / TM) // 24

// ---------------- smem layout (bytes) ----------------
#define SM_TOK   0                       // 128 ints
#define SM_BIAS  512                     // 512 floats (full row)
#define SM_X     4096                    // resident X: 8 slabs x 16KB
#define XSLAB    16384
#define SM_W     (SM_X + NCH * XSLAB)    // 135168: W ring
#define WSTG     16384
#define SMEM_TOTAL (SM_W + WSTAGE * WSTG)   // 200704 (1 CTA/SM)

// SW128 swizzle for 128B rows
#define SWZ(off) ((off) ^ (((off) >> 3) & 0x70))

__device__ int g_cnt[NUM_E];
__device__ int g_tok[NUM_E * CAPACITY];   // slot -> token id

// fp16 operands: xg permuted by expert slot; wf expert-major
__device__ __half g_xg[(size_t)NUM_E * CAPACITY * IN_F]; // 192 MB
__device__ __half g_wf[(size_t)NUM_E * OUT_F * IN_F];    // 32 MB

// ---------------- PTX helpers ----------------
__device__ __forceinline__ uint32_t smem_u32(const void* p) {
    uint32_t a;
    asm("{ .reg .u64 t; cvta.to.shared.u64 t, %1; cvt.u32.u64 %0, t; }"
        : "=r"(a) : "l"(p));
    return a;
}
__device__ __forceinline__ void cp16(uint32_t dst, const void* src) {
    asm volatile("cp.async.cg.shared.global [%0], [%1], 16;"
                 :: "r"(dst), "l"(src));
}
__device__ __forceinline__ void cp_commit() {
    asm volatile("cp.async.commit_group;" ::: "memory");
}
template <int N>
__device__ __forceinline__ void cp_wait() {
    asm volatile("cp.async.wait_group %0;" :: "n"(N) : "memory");
}
__device__ __forceinline__ void ldsm4(uint32_t* r, uint32_t a) {
    asm volatile("ldmatrix.sync.aligned.m8n8.x4.shared.b16 {%0,%1,%2,%3}, [%4];"
                 : "=r"(r[0]), "=r"(r[1]), "=r"(r[2]), "=r"(r[3]) : "r"(a));
}
__device__ __forceinline__ void mma16816(float* d, const uint32_t* a,
                                         const uint32_t* b) {
    asm volatile(
        "mma.sync.aligned.m16n8k16.row.col.f32.f16.f16.f32 "
        "{%0,%1,%2,%3}, {%4,%5,%6,%7}, {%8,%9}, {%0,%1,%2,%3};"
        : "+f"(d[0]), "+f"(d[1]), "+f"(d[2]), "+f"(d[3])
        : "r"(a[0]), "r"(a[1]), "r"(a[2]), "r"(a[3]), "r"(b[0]), "r"(b[1]));
}

// fp32x16 -> fp16x16 pack
__device__ __forceinline__ void cvt16(const float4* v, uint32_t* H) {
    const float* f = (const float*)v;
#pragma unroll
    for (int j = 0; j < 8; j++) {
        __half h0 = __float2half_rn(f[2 * j]);
        __half h1 = __float2half_rn(f[2 * j + 1]);
        H[j] = ((uint32_t)__half_as_ushort(h1) << 16) | __half_as_ushort(h0);
    }
}

// ---------------- pre-pass: w -> fp16 (+ counter zero in block 0) ----------
__global__ __launch_bounds__(256)
void k_cvt(const float* __restrict__ src, __half* __restrict__ dst, int n16) {
    if (blockIdx.x == 0 && threadIdx.x < NUM_E) g_cnt[threadIdx.x] = 0;
    int g = blockIdx.x * blockDim.x + threadIdx.x;
    if (g >= n16) return;
    const float4* s = (const float4*)(src + (size_t)g * 16);
    float4 v[4] = {s[0], s[1], s[2], s[3]};
    uint32_t H[8];
    cvt16(v, H);
    uint4* d = (uint4*)(dst + (size_t)g * 16);
    d[0] = make_uint4(H[0], H[1], H[2], H[3]);
    d[1] = make_uint4(H[4], H[5], H[6], H[7]);
}

// ---------------- fused route + x->fp16 permuted write ----------------
#define RBLK 256
__global__ __launch_bounds__(RBLK)
void k_route(const float* __restrict__ x, const int* __restrict__ eid,
             float* __restrict__ out) {
    __shared__ int s_slot[RBLK];
    __shared__ int s_hist[NUM_E];
    __shared__ int s_base[NUM_E];
    __shared__ int s_cur[NUM_E];

    const int tid = threadIdx.x;
    const int t0  = blockIdx.x * RBLK;

    int e = eid[t0 + tid];
    if (tid < NUM_E) { s_hist[tid] = 0; s_cur[tid] = 0; }
    __syncthreads();
    atomicAdd(&s_hist[e], 1);
    __syncthreads();
    if (tid < NUM_E) {
        int h = s_hist[tid];
        s_base[tid] = h ? atomicAdd(&g_cnt[tid], h) : 0;
    }
    __syncthreads();
    {
        int r = s_base[e] + atomicAdd(&s_cur[e], 1);
        if (r < CAPACITY) {
            int slot = e * CAPACITY + r;
            g_tok[slot] = t0 + tid;
            s_slot[tid] = slot;
        } else {
            s_slot[tid] = -1;
        }
    }
    __syncthreads();

    const int lane = tid & 31;
    const int wrp  = tid >> 5;
#pragma unroll 4
    for (int i = 0; i < 32; i++) {
        const int row = wrp * 32 + i;
        const int slot = s_slot[row];
        const float* src = x + (size_t)(t0 + row) * IN_F + lane * 16;
        if (slot >= 0) {
            float4 v[4] = {*(const float4*)(src + 0), *(const float4*)(src + 4),
                           *(const float4*)(src + 8), *(const float4*)(src + 12)};
            uint32_t H[8];
            cvt16(v, H);
            uint4* d = (uint4*)(g_xg + (size_t)slot * IN_F + lane * 16);
            d[0] = make_uint4(H[0], H[1], H[2], H[3]);
            d[1] = make_uint4(H[4], H[5], H[6], H[7]);
        } else {
            float4 z = make_float4(0.f, 0.f, 0.f, 0.f);
            float4* o = (float4*)(out + (size_t)(t0 + row) * OUT_F + lane * 16);
            o[0] = z; o[1] = z; o[2] = z; o[3] = z;
        }
    }
}

// ---------------- main GEMM: X-resident CTA, loops 4 N-tiles ----------------
__global__ __launch_bounds__(THREADS, 1)
void k_gemm(const float* __restrict__ bias, float* __restrict__ out) {
    extern __shared__ char smem[];

    const int e = blockIdx.y;
    int cnt = g_cnt[e];
    if (cnt > CAPACITY) cnt = CAPACITY;
    const int m0 = blockIdx.x * TM;
    if (m0 >= cnt) return;

    const int tid  = threadIdx.x;
    const int lane = tid & 31;
    const int wid  = tid >> 5;

    int*   stok  = (int*)(smem + SM_TOK);
    float* sbias = (float*)(smem + SM_BIAS);

    if (tid < TM) {
        stok[tid] = (m0 + tid < cnt) ? g_tok[e * CAPACITY + m0 + tid] : 0;
    }
    *(float2*)&sbias[tid * 2] = *(const float2*)&bias[e * OUT_F + tid * 2];

    const uint32_t sb = smem_u32(smem);
    const size_t xrow0 = (size_t)(e * CAPACITY + m0) * IN_F;
    const size_t wbase = (size_t)e * OUT_F * IN_F;

    // ---- issue resident X load: 8192 granules, 32 per thread, one group ----
    {
#pragma unroll
        for (int i = 0; i < 32; i++) {
            int g = tid + i * THREADS;            // 0..8191
            int slab = g >> 10;                   // K chunk 0..7
            int idx  = g & 1023;
            int row = idx >> 3, c8 = idx & 7;
            uint32_t dst = sb + SM_X + slab * XSLAB
                         + SWZ((uint32_t)(row * 128 + c8 * 16));
            cp16(dst, g_xg + xrow0 + (size_t)row * IN_F + slab * KC + c8 * 8);
        }
        cp_commit();
    }

    // ---- W chunk issue: cw = n*8 + c ----
    auto issueW = [&](int cw) {
        const int n = cw >> 3, c = cw & 7;
        const uint32_t stg = sb + SM_W + (cw & 3) * WSTG;
#pragma unroll
        for (int i = 0; i < 4; i++) {
            int g = tid + i * THREADS;            // 0..1023
            int row = g >> 3, c8 = g & 7;
            uint32_t dst = stg + SWZ((uint32_t)(row * 128 + c8 * 16));
            cp16(dst, g_wf + wbase + (size_t)(n * TN + row) * IN_F
                      + c * KC + c8 * 8);
        }
        cp_commit();
    };

    // per-warp ldmatrix address precompute
    const int aw = (wid >> 2) * 64;  // warp M offset: 2 groups of 64
    const int bw = (wid & 3) * 32;   // warp N offset: 4 groups of 32

    uint32_t a_off[4], a_mask[4];
    {
        int ar = lane & 15;
#pragma unroll
        for (int fi = 0; fi < 4; fi++) {
            int r = aw + fi * 16 + ar;
            a_off[fi] = (uint32_t)(r * 128);
            a_mask[fi] = (r & 7) * 16;
        }
    }
    const uint32_t a_klane = (lane & 16) ? 16u : 0u;

    uint32_t b_off[2], b_mask[2];
    {
        int br = (lane & 7) + ((lane & 16) ? 8 : 0);
#pragma unroll
        for (int jp = 0; jp < 2; jp++) {
            int r = bw + jp * 16 + br;
            b_off[jp] = (uint32_t)(r * 128);
            b_mask[jp] = (r & 7) * 16;
        }
    }
    const uint32_t b_klane = (lane & 8) ? 16u : 0u;

    // epilogue lane mapping (constant across n)
    const int r_in = lane >> 2;          // 0..7
    const int c_in = (lane & 3) * 2;     // 0,2,4,6
    int  erow[8];
    bool vld[8];
#pragma unroll
    for (int fi = 0; fi < 4; fi++) {
#pragma unroll
        for (int h = 0; h < 2; h++) {
            const int row = aw + fi * 16 + h * 8 + r_in;
            erow[fi * 2 + h] = row;
            vld[fi * 2 + h] = (m0 + row) < cnt;
        }
    }

    float acc[4][4][4];
#pragma unroll
    for (int i = 0; i < 4; i++)
#pragma unroll
        for (int j = 0; j < 4; j++)
#pragma unroll
            for (int q = 0; q < 4; q++) acc[i][j][q] = 0.f;

    // ---- prologue: X group + 3 W chunks in flight ----
    issueW(0);
    issueW(1);
    issueW(2);

    for (int cw = 0; cw < NCW; cw++) {
        const int c = cw & 7;
        if (cw <= NCW - 3)      cp_wait<2>();   // X..w_cw complete
        else if (cw == NCW - 2) cp_wait<1>();
        else                    cp_wait<0>();
        __syncthreads();

        if (cw + 3 < NCW) issueW(cw + 3);

        const uint32_t xs = sb + SM_X + c * XSLAB;
        const uint32_t ws = sb + SM_W + (cw & 3) * WSTG;

        // register-pipelined s-loop (fragment double buffer)
        uint32_t xf[2][4][4], wf[2][2][4];
#pragma unroll
        for (int fi = 0; fi < 4; fi++)
            ldsm4(xf[0][fi], xs + a_off[fi] + (a_klane ^ a_mask[fi]));
#pragma unroll
        for (int jp = 0; jp < 2; jp++)
            ldsm4(wf[0][jp], ws + b_off[jp] + (b_klane ^ b_mask[jp]));

#pragma unroll
        for (int s = 0; s < 4; s++) {
            const int cur = s & 1, nxt = cur ^ 1;
            if (s < 3) {
                const uint32_t kcol = (uint32_t)((s + 1) * 32);
#pragma unroll
                for (int fi = 0; fi < 4; fi++)
                    ldsm4(xf[nxt][fi], xs + a_off[fi] + ((kcol + a_klane) ^ a_mask[fi]));
#pragma unroll
                for (int jp = 0; jp < 2; jp++)
                    ldsm4(wf[nxt][jp], ws + b_off[jp] + ((kcol + b_klane) ^ b_mask[jp]));
            }
#pragma unroll
            for (int fi = 0; fi < 4; fi++) {
#pragma unroll
                for (int j = 0; j < 4; j++) {
                    mma16816(acc[fi][j], xf[cur][fi], &wf[cur][j >> 1][(j & 1) * 2]);
                }
            }
        }

        // ---- per-n epilogue after the last chunk of this n-tile ----
        if (c == 7) {
            const int n0 = (cw >> 3) * TN;
            float2 bv[4];
#pragma unroll
            for (int j = 0; j < 4; j++)
                bv[j] = *(const float2*)&sbias[n0 + bw + j * 8 + c_in];

#pragma unroll
            for (int g8 = 0; g8 < 8; g8++) {
                if (vld[g8]) {
                    const int tok = stok[erow[g8]];
                    float* op = out + (size_t)tok * OUT_F + n0 + bw + c_in;
                    const int fi = g8 >> 1, h = g8 & 1;
#pragma unroll
                    for (int j = 0; j < 4; j++) {
                        float2 v = make_float2(acc[fi][j][h * 2 + 0] + bv[j].x,
                                               acc[fi][j][h * 2 + 1] + bv[j].y);
                        *(float2*)(op + j * 8) = v;
                    }
                }
            }
#pragma unroll
            for (int i = 0; i < 4; i++)
#pragma unroll
                for (int j = 0; j < 4; j++)
#pragma unroll
                    for (int q = 0; q < 4; q++) acc[i][j][q] = 0.f;
        }
    }
}

// ---------------- launch ----------------
extern "C" void kernel_launch(void* const* d_in, const int* in_sizes, int n_in,
                              void* d_out, int out_size) {
    const float* x    = (const float*)d_in[0];
    const float* wght = (const float*)d_in[1];
    const float* bias = (const float*)d_in[2];
    const int*   eid  = (const int*)d_in[3];
    float* out = (float*)d_out;

    cudaFuncSetAttribute(k_gemm, cudaFuncAttributeMaxDynamicSharedMemorySize,
                         SMEM_TOTAL);

    __half* wf;
    cudaGetSymbolAddress((void**)&wf, g_wf);

    // k_cvt block 0 zeros g_cnt; k_route (stream-ordered after) sees zeros.
    const int nw16 = NUM_E * OUT_F * IN_F / 16;      // 1048576
    k_cvt<<<nw16 / 256, 256>>>(wght, wf, nw16);

    k_route<<<NTOK / RBLK, RBLK>>>(x, eid, out);

    dim3 grid(MTILES, NUM_E);
    k_gemm<<<grid, THREADS, SMEM_TOTAL>>>(bias, out);
}